// round 15
// baseline (speedup 1.0000x reference)
#include <cuda_runtime.h>
#include <cuda_fp16.h>
#include <cstdint>

#define N_NODES 100000
#define N_EDGES 1600000
#define F 128
#define SCAN_B 1024
#define NPART ((N_NODES + SCAN_B - 1) / SCAN_B)   // 98
#define NB_EDGES4 ((N_EDGES / 4 + 255) / 256)     // 1563 (int4 edges)
#define NB_EDGES8 ((N_EDGES / 8 + 255) / 256)     // 782  (2x int4 edges)
#define NB_CONV8 ((N_NODES * 16 + 255) / 256)     // 6250 (8 floats per thread)

// ---------------- device scratch (allocation-free rule) ----------------
// NOTE: g_deg_* rely on zero-init at module load; scan_final_kernel resets
// them to zero after consuming, so every kernel_launch call sees zeros.
__device__ __align__(16) __half g_h16[(size_t)N_NODES * F];  // 25.6 MB (features / h1)
__device__ __align__(16) __half g_a16[(size_t)N_NODES * F];  // 25.6 MB (aggregate out)
__device__ int   g_deg_src[N_NODES];
__device__ int   g_deg_dst[N_NODES];
__device__ float g_rs_src[N_NODES];
__device__ float g_rs_dst[N_NODES];
__device__ int   g_rowptr[N_NODES + 1];
__device__ int   g_cursor[N_NODES];
__device__ int   g_col[N_EDGES];                  // 6.4 MB
__device__ int   g_part[NPART];
__device__ __align__(16) unsigned short g_Wh[2][128 * 128];  // fp16 W

// ---------------- mma.sync helpers (portable PTX, sm_80+) ----------------
__device__ __forceinline__ uint32_t smem_u32(const void* p) {
    uint32_t a;
    asm("{ .reg .u64 t; cvta.to.shared.u64 t, %1; cvt.u32.u64 %0, t; }"
        : "=r"(a) : "l"(p));
    return a;
}
#define LDSM_X4(r, addr) \
    asm volatile("ldmatrix.sync.aligned.m8n8.x4.shared.b16 {%0,%1,%2,%3}, [%4];" \
                 : "=r"((r)[0]), "=r"((r)[1]), "=r"((r)[2]), "=r"((r)[3]) \
                 : "r"(addr))
#define LDSM_X4_T(r, addr) \
    asm volatile("ldmatrix.sync.aligned.m8n8.x4.trans.shared.b16 {%0,%1,%2,%3}, [%4];" \
                 : "=r"((r)[0]), "=r"((r)[1]), "=r"((r)[2]), "=r"((r)[3]) \
                 : "r"(addr))
#define MMA_FP16(c, a, b0, b1) \
    asm volatile("mma.sync.aligned.m16n8k16.row.col.f32.f16.f16.f32 " \
                 "{%0,%1,%2,%3}, {%4,%5,%6,%7}, {%8,%9}, {%0,%1,%2,%3};" \
                 : "+f"((c)[0]), "+f"((c)[1]), "+f"((c)[2]), "+f"((c)[3]) \
                 : "r"((a)[0]), "r"((a)[1]), "r"((a)[2]), "r"((a)[3]), \
                   "r"(b0), "r"(b1))

// ---------------- K1: build fp16 W + degree histogram (grid-partitioned) --
// src/dst are int32 (JAX x64-disable downcasts the reference's int64 arrays).
// Degrees were left zeroed by the previous call's scan_final (or module load).
__global__ void count_w_kernel(const int* __restrict__ src,
                               const int* __restrict__ dst,
                               const float* __restrict__ W1,
                               const float* __restrict__ W2) {
    int b = blockIdx.x;
    int tid = threadIdx.x;
    if (b < 64) {
        int idx = b * 256 + tid;                        // 0..16383
        g_Wh[0][idx] = __half_as_ushort(__float2half_rn(W1[idx]));
    } else if (b < 128) {
        int idx = (b - 64) * 256 + tid;
        g_Wh[1][idx] = __half_as_ushort(__float2half_rn(W2[idx]));
    } else {
        int t = (b - 128) * 256 + tid;                  // 8 edges per thread
        if (t < N_EDGES / 8) {
            int4 s0 = __ldg(((const int4*)src) + 2 * t);
            int4 s1 = __ldg(((const int4*)src) + 2 * t + 1);
            int4 d0 = __ldg(((const int4*)dst) + 2 * t);
            int4 d1 = __ldg(((const int4*)dst) + 2 * t + 1);
            atomicAdd(&g_deg_src[s0.x], 1); atomicAdd(&g_deg_src[s0.y], 1);
            atomicAdd(&g_deg_src[s0.z], 1); atomicAdd(&g_deg_src[s0.w], 1);
            atomicAdd(&g_deg_src[s1.x], 1); atomicAdd(&g_deg_src[s1.y], 1);
            atomicAdd(&g_deg_src[s1.z], 1); atomicAdd(&g_deg_src[s1.w], 1);
            atomicAdd(&g_deg_dst[d0.x], 1); atomicAdd(&g_deg_dst[d0.y], 1);
            atomicAdd(&g_deg_dst[d0.z], 1); atomicAdd(&g_deg_dst[d0.w], 1);
            atomicAdd(&g_deg_dst[d1.x], 1); atomicAdd(&g_deg_dst[d1.y], 1);
            atomicAdd(&g_deg_dst[d1.z], 1); atomicAdd(&g_deg_dst[d1.w], 1);
        }
    }
}

// K2: per-block sums of deg_dst (shuffle reduce, 1 barrier).
__global__ void scan_block_sums_kernel() {
    __shared__ int wsum[32];
    int tid = threadIdx.x;
    int lane = tid & 31, w = tid >> 5;
    int i = blockIdx.x * SCAN_B + tid;
    int v = (i < N_NODES) ? g_deg_dst[i] : 0;
    #pragma unroll
    for (int off = 16; off > 0; off >>= 1)
        v += __shfl_xor_sync(0xFFFFFFFFu, v, off);
    if (lane == 0) wsum[w] = v;
    __syncthreads();
    if (w == 0) {
        int q = wsum[lane];
        #pragma unroll
        for (int off = 16; off > 0; off >>= 1)
            q += __shfl_xor_sync(0xFFFFFFFFu, q, off);
        if (lane == 0) g_part[blockIdx.x] = q;
    }
}

// K3: final scan (shuffle-based). Also computes rs factors and RESETS the
// degree counters for the next call (zeroed-counter invariant).
__global__ void scan_final_kernel() {
    __shared__ int wsum[32];
    __shared__ int wpre[32];
    __shared__ int sh_base;
    int tid = threadIdx.x;
    int lane = tid & 31, w = tid >> 5;
    int b = blockIdx.x;
    int i = b * SCAN_B + tid;

    int p = (tid < b) ? g_part[tid] : 0;
    #pragma unroll
    for (int off = 16; off > 0; off >>= 1)
        p += __shfl_xor_sync(0xFFFFFFFFu, p, off);
    if (lane == 0) wsum[w] = p;
    __syncthreads();
    if (w == 0) {
        int q = wsum[lane];
        #pragma unroll
        for (int off = 16; off > 0; off >>= 1)
            q += __shfl_xor_sync(0xFFFFFFFFu, q, off);
        if (lane == 0) sh_base = q;
    }
    __syncthreads();
    int base = sh_base;

    int v = (i < N_NODES) ? g_deg_dst[i] : 0;
    int s = v;
    #pragma unroll
    for (int off = 1; off < 32; off <<= 1) {
        int t = __shfl_up_sync(0xFFFFFFFFu, s, off);
        if (lane >= off) s += t;
    }
    if (lane == 31) wsum[w] = s;
    __syncthreads();
    if (w == 0) {
        int q = wsum[lane];
        int qs = q;
        #pragma unroll
        for (int off = 1; off < 32; off <<= 1) {
            int t = __shfl_up_sync(0xFFFFFFFFu, qs, off);
            if (lane >= off) qs += t;
        }
        wpre[lane] = qs - q;
    }
    __syncthreads();

    if (i < N_NODES) {
        int excl = s - v + wpre[w] + base;
        g_rowptr[i] = excl;
        g_cursor[i] = excl;
        int ds = g_deg_src[i]; if (ds < 1) ds = 1;
        int dd = v; if (dd < 1) dd = 1;
        g_rs_src[i] = rsqrtf((float)ds);
        g_rs_dst[i] = rsqrtf((float)dd);
        g_deg_src[i] = 0;
        g_deg_dst[i] = 0;
    }
    if (b == NPART - 1 && tid == 0) g_rowptr[N_NODES] = N_EDGES;
}

// K4: feature conversion (streaming blocks FIRST) + CSR fill (scatter last).
// Conv: 8 floats/thread (2x LDG.128 + 1x STG.128 of packed halves).
__global__ void fill_conv_kernel(const int* __restrict__ src,
                                 const int* __restrict__ dst,
                                 const float* __restrict__ feat) {
    int b = blockIdx.x;
    int tid = threadIdx.x;
    if (b < NB_CONV8) {
        size_t t = (size_t)b * 256 + tid;                // 8-float chunk index
        if (t < (size_t)N_NODES * (F / 8)) {
            int row = (int)(t >> 4);                     // 16 chunks per row
            float rs = __ldg(&g_rs_src[row]);
            float4 v0 = __ldg(((const float4*)feat) + 2 * t);
            float4 v1 = __ldg(((const float4*)feat) + 2 * t + 1);
            uint4 o;
            *(__half2*)&o.x = __floats2half2_rn(v0.x * rs, v0.y * rs);
            *(__half2*)&o.y = __floats2half2_rn(v0.z * rs, v0.w * rs);
            *(__half2*)&o.z = __floats2half2_rn(v1.x * rs, v1.y * rs);
            *(__half2*)&o.w = __floats2half2_rn(v1.z * rs, v1.w * rs);
            *(uint4*)(g_h16 + t * 8) = o;
        }
    } else {
        int t = (b - NB_CONV8) * 256 + tid;              // int4 edge index
        if (t < N_EDGES / 4) {
            int4 s = __ldg(((const int4*)src) + t);
            int4 d = __ldg(((const int4*)dst) + t);
            g_col[atomicAdd(&g_cursor[d.x], 1)] = s.x;
            g_col[atomicAdd(&g_cursor[d.y], 1)] = s.y;
            g_col[atomicAdd(&g_cursor[d.z], 1)] = s.z;
            g_col[atomicAdd(&g_cursor[d.w], 1)] = s.w;
        }
    }
}

// ---------------- aggregation: one warp per node (R12 form, proven) ------
// out16[n,:] = fp16( rs_dst[n] * sum_{s in N_in(n)} hin[s,:] )
__global__ void __launch_bounds__(256)
aggregate16_kernel(const __half* __restrict__ hin, __half* __restrict__ out16) {
    int node = (blockIdx.x * blockDim.x + threadIdx.x) >> 5;
    int lane = threadIdx.x & 31;
    if (node >= N_NODES) return;

    int beg = __ldg(&g_rowptr[node]);
    int end = __ldg(&g_rowptr[node + 1]);

    float a0 = 0.f, a1 = 0.f, a2 = 0.f, a3 = 0.f;
    int e = beg;

    #define ACC(v) do { \
        float2 fa = __half22float2(*(const __half2*)&(v).x); \
        float2 fb = __half22float2(*(const __half2*)&(v).y); \
        a0 += fa.x; a1 += fa.y; a2 += fb.x; a3 += fb.y; } while (0)

    for (; e + 8 <= end; e += 8) {
        int c0 = __ldg(&g_col[e]);
        int c1 = __ldg(&g_col[e + 1]);
        int c2 = __ldg(&g_col[e + 2]);
        int c3 = __ldg(&g_col[e + 3]);
        int c4 = __ldg(&g_col[e + 4]);
        int c5 = __ldg(&g_col[e + 5]);
        int c6 = __ldg(&g_col[e + 6]);
        int c7 = __ldg(&g_col[e + 7]);
        uint2 v0 = __ldg((const uint2*)(hin + (size_t)c0 * F + lane * 4));
        uint2 v1 = __ldg((const uint2*)(hin + (size_t)c1 * F + lane * 4));
        uint2 v2 = __ldg((const uint2*)(hin + (size_t)c2 * F + lane * 4));
        uint2 v3 = __ldg((const uint2*)(hin + (size_t)c3 * F + lane * 4));
        uint2 v4 = __ldg((const uint2*)(hin + (size_t)c4 * F + lane * 4));
        uint2 v5 = __ldg((const uint2*)(hin + (size_t)c5 * F + lane * 4));
        uint2 v6 = __ldg((const uint2*)(hin + (size_t)c6 * F + lane * 4));
        uint2 v7 = __ldg((const uint2*)(hin + (size_t)c7 * F + lane * 4));
        ACC(v0); ACC(v1); ACC(v2); ACC(v3);
        ACC(v4); ACC(v5); ACC(v6); ACC(v7);
    }
    if (e + 4 <= end) {
        int c0 = __ldg(&g_col[e]);
        int c1 = __ldg(&g_col[e + 1]);
        int c2 = __ldg(&g_col[e + 2]);
        int c3 = __ldg(&g_col[e + 3]);
        uint2 v0 = __ldg((const uint2*)(hin + (size_t)c0 * F + lane * 4));
        uint2 v1 = __ldg((const uint2*)(hin + (size_t)c1 * F + lane * 4));
        uint2 v2 = __ldg((const uint2*)(hin + (size_t)c2 * F + lane * 4));
        uint2 v3 = __ldg((const uint2*)(hin + (size_t)c3 * F + lane * 4));
        ACC(v0); ACC(v1); ACC(v2); ACC(v3);
        e += 4;
    }
    if (e + 2 <= end) {
        int c0 = __ldg(&g_col[e]);
        int c1 = __ldg(&g_col[e + 1]);
        uint2 v0 = __ldg((const uint2*)(hin + (size_t)c0 * F + lane * 4));
        uint2 v1 = __ldg((const uint2*)(hin + (size_t)c1 * F + lane * 4));
        ACC(v0); ACC(v1);
        e += 2;
    }
    if (e < end) {
        int c0 = __ldg(&g_col[e]);
        uint2 v0 = __ldg((const uint2*)(hin + (size_t)c0 * F + lane * 4));
        ACC(v0);
    }
    #undef ACC

    float rd = __ldg(&g_rs_dst[node]);
    uint2 o;
    *(__half2*)&o.x = __floats2half2_rn(a0 * rd, a1 * rd);
    *(__half2*)&o.y = __floats2half2_rn(a2 * rd, a3 * rd);
    *(uint2*)(out16 + (size_t)node * F + lane * 4) = o;
}

// ---------------- tensor-core GEMM: single-pass fp16 ---------------------
#define PADK 136
#define ROWB (PADK * 2)              // 272 bytes
#define TILE_BYTES (128 * ROWB)      // 34816
#define GEMM_SMEM_BYTES (2 * TILE_BYTES)  // 69632

template <int HALF_OUT>
__global__ void __launch_bounds__(256, 2)
mma_gemm_kernel(const __half* __restrict__ A16,
                const unsigned short* __restrict__ Wh,
                const float* __restrict__ bias,
                float* __restrict__ out32,
                __half* __restrict__ out16) {
    extern __shared__ __align__(16) unsigned char smem[];
    unsigned char* sA = smem;
    unsigned char* sW = smem + TILE_BYTES;

    int tid  = threadIdx.x;
    int wid  = tid >> 5;
    int lane = tid & 31;
    int row0 = blockIdx.x * 128;

    {
        int r = tid >> 1, hf = tid & 1;
        const uint4* srcw = (const uint4*)(Wh + r * 128 + hf * 64);
        uint4* dstw = (uint4*)(sW + r * ROWB + hf * 128);
        #pragma unroll
        for (int i = 0; i < 8; ++i) dstw[i] = __ldg(srcw + i);
    }
    {
        int r = tid >> 1, hf = tid & 1;
        int row = row0 + r;
        uint4* dsta = (uint4*)(sA + r * ROWB + hf * 128);
        if (row < N_NODES) {
            const uint4* srca = (const uint4*)(A16 + (size_t)row * F + hf * 64);
            #pragma unroll
            for (int i = 0; i < 8; ++i) dsta[i] = __ldg(srca + i);
        } else {
            uint4 z = make_uint4(0, 0, 0, 0);
            #pragma unroll
            for (int i = 0; i < 8; ++i) dsta[i] = z;
        }
    }
    __syncthreads();

    int m0 = wid * 16;
    float acc[16][4];
    #pragma unroll
    for (int nt = 0; nt < 16; ++nt)
        #pragma unroll
        for (int c = 0; c < 4; ++c) acc[nt][c] = 0.f;

    uint32_t aoff = (uint32_t)(m0 + (lane & 15)) * ROWB + (uint32_t)(lane >> 4) * 16;
    uint32_t a_base = smem_u32(sA) + aoff;
    uint32_t wrow = (uint32_t)(lane & 15) * ROWB + (uint32_t)(lane >> 4) * 16;
    uint32_t w_base = smem_u32(sW) + wrow;

    #pragma unroll
    for (int ks = 0; ks < 8; ++ks) {
        uint32_t a[4];
        LDSM_X4(a, a_base + ks * 32);
        uint32_t w_k = w_base + (uint32_t)ks * 16 * ROWB;
        #pragma unroll
        for (int nt2 = 0; nt2 < 8; ++nt2) {
            uint32_t w[4];
            LDSM_X4_T(w, w_k + nt2 * 32);
            MMA_FP16(acc[2 * nt2],     a, w[0], w[1]);
            MMA_FP16(acc[2 * nt2 + 1], a, w[2], w[3]);
        }
    }

    int r0 = row0 + m0 + (lane >> 2);
    int cb = 2 * (lane & 3);
    float rs0 = 0.f, rs1 = 0.f;
    if (HALF_OUT) {
        if (r0 < N_NODES)     rs0 = __ldg(&g_rs_src[r0]);
        if (r0 + 8 < N_NODES) rs1 = __ldg(&g_rs_src[r0 + 8]);
    }
    #pragma unroll
    for (int nt = 0; nt < 16; ++nt) {
        int n = nt * 8 + cb;
        float bx = __ldg(&bias[n]), by = __ldg(&bias[n + 1]);
        float v0x = fmaxf(acc[nt][0] + bx, 0.f);
        float v0y = fmaxf(acc[nt][1] + by, 0.f);
        float v1x = fmaxf(acc[nt][2] + bx, 0.f);
        float v1y = fmaxf(acc[nt][3] + by, 0.f);
        if (HALF_OUT) {
            if (r0 < N_NODES)
                *(__half2*)(out16 + (size_t)r0 * F + n) = __floats2half2_rn(v0x * rs0, v0y * rs0);
            if (r0 + 8 < N_NODES)
                *(__half2*)(out16 + (size_t)(r0 + 8) * F + n) = __floats2half2_rn(v1x * rs1, v1y * rs1);
        } else {
            if (r0 < N_NODES)
                *(float2*)(out32 + (size_t)r0 * F + n) = make_float2(v0x, v0y);
            if (r0 + 8 < N_NODES)
                *(float2*)(out32 + (size_t)(r0 + 8) * F + n) = make_float2(v1x, v1y);
        }
    }
}

// ---------------- host launch ----------------
extern "C" void kernel_launch(void* const* d_in, const int* in_sizes, int n_in,
                              void* d_out, int out_size) {
    const float* features = (const float*)d_in[0];
    const float* W1       = (const float*)d_in[1];
    const float* b1       = (const float*)d_in[2];
    const float* W2       = (const float*)d_in[3];
    const float* b2       = (const float*)d_in[4];
    const int*   src      = (const int*)d_in[5];
    const int*   dst      = (const int*)d_in[6];
    float*       out      = (float*)d_out;

    __half *h16 = nullptr, *a16 = nullptr;
    unsigned short *wh = nullptr;
    cudaGetSymbolAddress((void**)&h16, g_h16);
    cudaGetSymbolAddress((void**)&a16, g_a16);
    cudaGetSymbolAddress((void**)&wh,  g_Wh);

    cudaFuncSetAttribute(mma_gemm_kernel<0>,
                         cudaFuncAttributeMaxDynamicSharedMemorySize, GEMM_SMEM_BYTES);
    cudaFuncSetAttribute(mma_gemm_kernel<1>,
                         cudaFuncAttributeMaxDynamicSharedMemorySize, GEMM_SMEM_BYTES);

    int nblk_aggw = (N_NODES * 32 + 255) / 256;   // one warp per node
    int nblk_gemm = (N_NODES + 127) / 128;        // 782

    // K1-K4: preprocessing (deterministic each call; degs were reset by
    // the previous call's scan_final — zeroed-counter invariant)
    count_w_kernel<<<128 + NB_EDGES8, 256>>>(src, dst, W1, W2);
    scan_block_sums_kernel<<<NPART, SCAN_B>>>();
    scan_final_kernel<<<NPART, SCAN_B>>>();
    fill_conv_kernel<<<NB_CONV8 + NB_EDGES4, 256>>>(src, dst, features);

    // K5-K6: layer 1   (h16 -> a16 -> h16)
    aggregate16_kernel<<<nblk_aggw, 256>>>(h16, a16);
    mma_gemm_kernel<1><<<nblk_gemm, 256, GEMM_SMEM_BYTES>>>(a16, wh, b1, nullptr, h16);

    // K7-K8: layer 2   (h16 -> a16 -> out fp32)
    aggregate16_kernel<<<nblk_aggw, 256>>>(h16, a16);
    mma_gemm_kernel<0><<<nblk_gemm, 256, GEMM_SMEM_BYTES>>>(a16, wh + 128 * 128, b2, out, nullptr);
}

// round 16
// speedup vs baseline: 1.0246x; 1.0246x over previous
#include <cuda_runtime.h>
#include <cuda_fp16.h>
#include <cstdint>

#define N_NODES 100000
#define N_EDGES 1600000
#define F 128
#define SCAN_B 1024
#define NPART ((N_NODES + SCAN_B - 1) / SCAN_B)   // 98
#define NB_EDGES4 ((N_EDGES / 4 + 255) / 256)     // 1563 (int4 edges)
#define NB_CONV  ((N_NODES * 32 + 255) / 256)     // 12500 (float4 elems)

// ---------------- device scratch (allocation-free rule) ----------------
// NOTE: g_deg_* rely on zero-init at module load; scan_final_kernel resets
// them to zero after consuming, so every kernel_launch call sees zeros.
__device__ __align__(16) __half g_h16[(size_t)N_NODES * F];  // 25.6 MB (features / h1)
__device__ __align__(16) __half g_a16[(size_t)N_NODES * F];  // 25.6 MB (aggregate out)
__device__ int   g_deg_src[N_NODES];
__device__ int   g_deg_dst[N_NODES];
__device__ float g_rs_src[N_NODES];
__device__ float g_rs_dst[N_NODES];
__device__ int   g_rowptr[N_NODES + 1];
__device__ __align__(16) int g_eoff[N_EDGES];     // 6.4 MB per-edge slot in dst bucket
__device__ __align__(16) int g_col[N_EDGES];      // 6.4 MB
__device__ int   g_part[NPART];
__device__ __align__(16) unsigned short g_Wh[2][128 * 128];  // fp16 W

// ---------------- mma.sync helpers (portable PTX, sm_80+) ----------------
__device__ __forceinline__ uint32_t smem_u32(const void* p) {
    uint32_t a;
    asm("{ .reg .u64 t; cvta.to.shared.u64 t, %1; cvt.u32.u64 %0, t; }"
        : "=r"(a) : "l"(p));
    return a;
}
#define LDSM_X4(r, addr) \
    asm volatile("ldmatrix.sync.aligned.m8n8.x4.shared.b16 {%0,%1,%2,%3}, [%4];" \
                 : "=r"((r)[0]), "=r"((r)[1]), "=r"((r)[2]), "=r"((r)[3]) \
                 : "r"(addr))
#define LDSM_X4_T(r, addr) \
    asm volatile("ldmatrix.sync.aligned.m8n8.x4.trans.shared.b16 {%0,%1,%2,%3}, [%4];" \
                 : "=r"((r)[0]), "=r"((r)[1]), "=r"((r)[2]), "=r"((r)[3]) \
                 : "r"(addr))
#define MMA_FP16(c, a, b0, b1) \
    asm volatile("mma.sync.aligned.m16n8k16.row.col.f32.f16.f16.f32 " \
                 "{%0,%1,%2,%3}, {%4,%5,%6,%7}, {%8,%9}, {%0,%1,%2,%3};" \
                 : "+f"((c)[0]), "+f"((c)[1]), "+f"((c)[2]), "+f"((c)[3]) \
                 : "r"((a)[0]), "r"((a)[1]), "r"((a)[2]), "r"((a)[3]), \
                   "r"(b0), "r"(b1))

// ---------------- K1: build fp16 W + degree histogram + slot capture -----
// src/dst are int32 (JAX x64-disable downcasts the reference's int64 arrays).
// Degrees were left zeroed by the previous call's scan_final (or module load).
// The dst atomicAdd's RETURN VALUE is this edge's slot within its dst bucket;
// storing it here makes the CSR fill pass atomic-free.
__global__ void count_w_kernel(const int* __restrict__ src,
                               const int* __restrict__ dst,
                               const float* __restrict__ W1,
                               const float* __restrict__ W2) {
    int b = blockIdx.x;
    int tid = threadIdx.x;
    if (b < 64) {
        int idx = b * 256 + tid;                        // 0..16383
        g_Wh[0][idx] = __half_as_ushort(__float2half_rn(W1[idx]));
    } else if (b < 128) {
        int idx = (b - 64) * 256 + tid;
        g_Wh[1][idx] = __half_as_ushort(__float2half_rn(W2[idx]));
    } else {
        int t = (b - 128) * 256 + tid;                  // int4 edge index
        if (t < N_EDGES / 4) {
            int4 s = __ldg(((const int4*)src) + t);
            int4 d = __ldg(((const int4*)dst) + t);
            atomicAdd(&g_deg_src[s.x], 1);
            atomicAdd(&g_deg_src[s.y], 1);
            atomicAdd(&g_deg_src[s.z], 1);
            atomicAdd(&g_deg_src[s.w], 1);
            int4 o;
            o.x = atomicAdd(&g_deg_dst[d.x], 1);
            o.y = atomicAdd(&g_deg_dst[d.y], 1);
            o.z = atomicAdd(&g_deg_dst[d.z], 1);
            o.w = atomicAdd(&g_deg_dst[d.w], 1);
            ((int4*)g_eoff)[t] = o;                     // coalesced
        }
    }
}

// K2: per-block sums of deg_dst (shuffle reduce, 1 barrier).
__global__ void scan_block_sums_kernel() {
    __shared__ int wsum[32];
    int tid = threadIdx.x;
    int lane = tid & 31, w = tid >> 5;
    int i = blockIdx.x * SCAN_B + tid;
    int v = (i < N_NODES) ? g_deg_dst[i] : 0;
    #pragma unroll
    for (int off = 16; off > 0; off >>= 1)
        v += __shfl_xor_sync(0xFFFFFFFFu, v, off);
    if (lane == 0) wsum[w] = v;
    __syncthreads();
    if (w == 0) {
        int q = wsum[lane];
        #pragma unroll
        for (int off = 16; off > 0; off >>= 1)
            q += __shfl_xor_sync(0xFFFFFFFFu, q, off);
        if (lane == 0) g_part[blockIdx.x] = q;
    }
}

// K3: final scan (shuffle-based). Also computes rs factors and RESETS the
// degree counters for the next call (zeroed-counter invariant).
__global__ void scan_final_kernel() {
    __shared__ int wsum[32];
    __shared__ int wpre[32];
    __shared__ int sh_base;
    int tid = threadIdx.x;
    int lane = tid & 31, w = tid >> 5;
    int b = blockIdx.x;
    int i = b * SCAN_B + tid;

    int p = (tid < b) ? g_part[tid] : 0;
    #pragma unroll
    for (int off = 16; off > 0; off >>= 1)
        p += __shfl_xor_sync(0xFFFFFFFFu, p, off);
    if (lane == 0) wsum[w] = p;
    __syncthreads();
    if (w == 0) {
        int q = wsum[lane];
        #pragma unroll
        for (int off = 16; off > 0; off >>= 1)
            q += __shfl_xor_sync(0xFFFFFFFFu, q, off);
        if (lane == 0) sh_base = q;
    }
    __syncthreads();
    int base = sh_base;

    int v = (i < N_NODES) ? g_deg_dst[i] : 0;
    int s = v;
    #pragma unroll
    for (int off = 1; off < 32; off <<= 1) {
        int t = __shfl_up_sync(0xFFFFFFFFu, s, off);
        if (lane >= off) s += t;
    }
    if (lane == 31) wsum[w] = s;
    __syncthreads();
    if (w == 0) {
        int q = wsum[lane];
        int qs = q;
        #pragma unroll
        for (int off = 1; off < 32; off <<= 1) {
            int t = __shfl_up_sync(0xFFFFFFFFu, qs, off);
            if (lane >= off) qs += t;
        }
        wpre[lane] = qs - q;
    }
    __syncthreads();

    if (i < N_NODES) {
        int excl = s - v + wpre[w] + base;
        g_rowptr[i] = excl;
        int ds = g_deg_src[i]; if (ds < 1) ds = 1;
        int dd = v; if (dd < 1) dd = 1;
        g_rs_src[i] = rsqrtf((float)ds);
        g_rs_dst[i] = rsqrtf((float)dd);
        g_deg_src[i] = 0;
        g_deg_dst[i] = 0;
    }
    if (b == NPART - 1 && tid == 0) g_rowptr[N_NODES] = N_EDGES;
}

// K4: CSR fill (ATOMIC-FREE: rowptr + captured slot) + feature conversion.
__global__ void fill_conv_kernel(const int* __restrict__ src,
                                 const int* __restrict__ dst,
                                 const float* __restrict__ feat) {
    int b = blockIdx.x;
    int tid = threadIdx.x;
    if (b < NB_EDGES4) {
        int t = b * 256 + tid;
        if (t < N_EDGES / 4) {
            int4 s = __ldg(((const int4*)src) + t);
            int4 d = __ldg(((const int4*)dst) + t);
            int4 o = __ldg(((const int4*)g_eoff) + t);
            g_col[__ldg(&g_rowptr[d.x]) + o.x] = s.x;
            g_col[__ldg(&g_rowptr[d.y]) + o.y] = s.y;
            g_col[__ldg(&g_rowptr[d.z]) + o.z] = s.z;
            g_col[__ldg(&g_rowptr[d.w]) + o.w] = s.w;
        }
    } else {
        size_t i = (size_t)(b - NB_EDGES4) * 256 + tid;   // float4 index
        if (i < (size_t)N_NODES * (F / 4)) {
            int row = (int)(i >> 5);
            float rs = __ldg(&g_rs_src[row]);
            float4 v = __ldg(((const float4*)feat) + i);
            *(__half2*)(g_h16 + i * 4)     = __floats2half2_rn(v.x * rs, v.y * rs);
            *(__half2*)(g_h16 + i * 4 + 2) = __floats2half2_rn(v.z * rs, v.w * rs);
        }
    }
}

// ---------------- aggregation: one warp per node (R12 form, proven) ------
// out16[n,:] = fp16( rs_dst[n] * sum_{s in N_in(n)} hin[s,:] )
__global__ void __launch_bounds__(256)
aggregate16_kernel(const __half* __restrict__ hin, __half* __restrict__ out16) {
    int node = (blockIdx.x * blockDim.x + threadIdx.x) >> 5;
    int lane = threadIdx.x & 31;
    if (node >= N_NODES) return;

    int beg = __ldg(&g_rowptr[node]);
    int end = __ldg(&g_rowptr[node + 1]);

    float a0 = 0.f, a1 = 0.f, a2 = 0.f, a3 = 0.f;
    int e = beg;

    #define ACC(v) do { \
        float2 fa = __half22float2(*(const __half2*)&(v).x); \
        float2 fb = __half22float2(*(const __half2*)&(v).y); \
        a0 += fa.x; a1 += fa.y; a2 += fb.x; a3 += fb.y; } while (0)

    for (; e + 8 <= end; e += 8) {
        int c0 = __ldg(&g_col[e]);
        int c1 = __ldg(&g_col[e + 1]);
        int c2 = __ldg(&g_col[e + 2]);
        int c3 = __ldg(&g_col[e + 3]);
        int c4 = __ldg(&g_col[e + 4]);
        int c5 = __ldg(&g_col[e + 5]);
        int c6 = __ldg(&g_col[e + 6]);
        int c7 = __ldg(&g_col[e + 7]);
        uint2 v0 = __ldg((const uint2*)(hin + (size_t)c0 * F + lane * 4));
        uint2 v1 = __ldg((const uint2*)(hin + (size_t)c1 * F + lane * 4));
        uint2 v2 = __ldg((const uint2*)(hin + (size_t)c2 * F + lane * 4));
        uint2 v3 = __ldg((const uint2*)(hin + (size_t)c3 * F + lane * 4));
        uint2 v4 = __ldg((const uint2*)(hin + (size_t)c4 * F + lane * 4));
        uint2 v5 = __ldg((const uint2*)(hin + (size_t)c5 * F + lane * 4));
        uint2 v6 = __ldg((const uint2*)(hin + (size_t)c6 * F + lane * 4));
        uint2 v7 = __ldg((const uint2*)(hin + (size_t)c7 * F + lane * 4));
        ACC(v0); ACC(v1); ACC(v2); ACC(v3);
        ACC(v4); ACC(v5); ACC(v6); ACC(v7);
    }
    if (e + 4 <= end) {
        int c0 = __ldg(&g_col[e]);
        int c1 = __ldg(&g_col[e + 1]);
        int c2 = __ldg(&g_col[e + 2]);
        int c3 = __ldg(&g_col[e + 3]);
        uint2 v0 = __ldg((const uint2*)(hin + (size_t)c0 * F + lane * 4));
        uint2 v1 = __ldg((const uint2*)(hin + (size_t)c1 * F + lane * 4));
        uint2 v2 = __ldg((const uint2*)(hin + (size_t)c2 * F + lane * 4));
        uint2 v3 = __ldg((const uint2*)(hin + (size_t)c3 * F + lane * 4));
        ACC(v0); ACC(v1); ACC(v2); ACC(v3);
        e += 4;
    }
    if (e + 2 <= end) {
        int c0 = __ldg(&g_col[e]);
        int c1 = __ldg(&g_col[e + 1]);
        uint2 v0 = __ldg((const uint2*)(hin + (size_t)c0 * F + lane * 4));
        uint2 v1 = __ldg((const uint2*)(hin + (size_t)c1 * F + lane * 4));
        ACC(v0); ACC(v1);
        e += 2;
    }
    if (e < end) {
        int c0 = __ldg(&g_col[e]);
        uint2 v0 = __ldg((const uint2*)(hin + (size_t)c0 * F + lane * 4));
        ACC(v0);
    }
    #undef ACC

    float rd = __ldg(&g_rs_dst[node]);
    uint2 o;
    *(__half2*)&o.x = __floats2half2_rn(a0 * rd, a1 * rd);
    *(__half2*)&o.y = __floats2half2_rn(a2 * rd, a3 * rd);
    *(uint2*)(out16 + (size_t)node * F + lane * 4) = o;
}

// ---------------- tensor-core GEMM: single-pass fp16 ---------------------
#define PADK 136
#define ROWB (PADK * 2)              // 272 bytes
#define TILE_BYTES (128 * ROWB)      // 34816
#define GEMM_SMEM_BYTES (2 * TILE_BYTES)  // 69632

template <int HALF_OUT>
__global__ void __launch_bounds__(256, 2)
mma_gemm_kernel(const __half* __restrict__ A16,
                const unsigned short* __restrict__ Wh,
                const float* __restrict__ bias,
                float* __restrict__ out32,
                __half* __restrict__ out16) {
    extern __shared__ __align__(16) unsigned char smem[];
    unsigned char* sA = smem;
    unsigned char* sW = smem + TILE_BYTES;

    int tid  = threadIdx.x;
    int wid  = tid >> 5;
    int lane = tid & 31;
    int row0 = blockIdx.x * 128;

    {
        int r = tid >> 1, hf = tid & 1;
        const uint4* srcw = (const uint4*)(Wh + r * 128 + hf * 64);
        uint4* dstw = (uint4*)(sW + r * ROWB + hf * 128);
        #pragma unroll
        for (int i = 0; i < 8; ++i) dstw[i] = __ldg(srcw + i);
    }
    {
        int r = tid >> 1, hf = tid & 1;
        int row = row0 + r;
        uint4* dsta = (uint4*)(sA + r * ROWB + hf * 128);
        if (row < N_NODES) {
            const uint4* srca = (const uint4*)(A16 + (size_t)row * F + hf * 64);
            #pragma unroll
            for (int i = 0; i < 8; ++i) dsta[i] = __ldg(srca + i);
        } else {
            uint4 z = make_uint4(0, 0, 0, 0);
            #pragma unroll
            for (int i = 0; i < 8; ++i) dsta[i] = z;
        }
    }
    __syncthreads();

    int m0 = wid * 16;
    float acc[16][4];
    #pragma unroll
    for (int nt = 0; nt < 16; ++nt)
        #pragma unroll
        for (int c = 0; c < 4; ++c) acc[nt][c] = 0.f;

    uint32_t aoff = (uint32_t)(m0 + (lane & 15)) * ROWB + (uint32_t)(lane >> 4) * 16;
    uint32_t a_base = smem_u32(sA) + aoff;
    uint32_t wrow = (uint32_t)(lane & 15) * ROWB + (uint32_t)(lane >> 4) * 16;
    uint32_t w_base = smem_u32(sW) + wrow;

    #pragma unroll
    for (int ks = 0; ks < 8; ++ks) {
        uint32_t a[4];
        LDSM_X4(a, a_base + ks * 32);
        uint32_t w_k = w_base + (uint32_t)ks * 16 * ROWB;
        #pragma unroll
        for (int nt2 = 0; nt2 < 8; ++nt2) {
            uint32_t w[4];
            LDSM_X4_T(w, w_k + nt2 * 32);
            MMA_FP16(acc[2 * nt2],     a, w[0], w[1]);
            MMA_FP16(acc[2 * nt2 + 1], a, w[2], w[3]);
        }
    }

    int r0 = row0 + m0 + (lane >> 2);
    int cb = 2 * (lane & 3);
    float rs0 = 0.f, rs1 = 0.f;
    if (HALF_OUT) {
        if (r0 < N_NODES)     rs0 = __ldg(&g_rs_src[r0]);
        if (r0 + 8 < N_NODES) rs1 = __ldg(&g_rs_src[r0 + 8]);
    }
    #pragma unroll
    for (int nt = 0; nt < 16; ++nt) {
        int n = nt * 8 + cb;
        float bx = __ldg(&bias[n]), by = __ldg(&bias[n + 1]);
        float v0x = fmaxf(acc[nt][0] + bx, 0.f);
        float v0y = fmaxf(acc[nt][1] + by, 0.f);
        float v1x = fmaxf(acc[nt][2] + bx, 0.f);
        float v1y = fmaxf(acc[nt][3] + by, 0.f);
        if (HALF_OUT) {
            if (r0 < N_NODES)
                *(__half2*)(out16 + (size_t)r0 * F + n) = __floats2half2_rn(v0x * rs0, v0y * rs0);
            if (r0 + 8 < N_NODES)
                *(__half2*)(out16 + (size_t)(r0 + 8) * F + n) = __floats2half2_rn(v1x * rs1, v1y * rs1);
        } else {
            if (r0 < N_NODES)
                *(float2*)(out32 + (size_t)r0 * F + n) = make_float2(v0x, v0y);
            if (r0 + 8 < N_NODES)
                *(float2*)(out32 + (size_t)(r0 + 8) * F + n) = make_float2(v1x, v1y);
        }
    }
}

// ---------------- host launch ----------------
extern "C" void kernel_launch(void* const* d_in, const int* in_sizes, int n_in,
                              void* d_out, int out_size) {
    const float* features = (const float*)d_in[0];
    const float* W1       = (const float*)d_in[1];
    const float* b1       = (const float*)d_in[2];
    const float* W2       = (const float*)d_in[3];
    const float* b2       = (const float*)d_in[4];
    const int*   src      = (const int*)d_in[5];
    const int*   dst      = (const int*)d_in[6];
    float*       out      = (float*)d_out;

    __half *h16 = nullptr, *a16 = nullptr;
    unsigned short *wh = nullptr;
    cudaGetSymbolAddress((void**)&h16, g_h16);
    cudaGetSymbolAddress((void**)&a16, g_a16);
    cudaGetSymbolAddress((void**)&wh,  g_Wh);

    cudaFuncSetAttribute(mma_gemm_kernel<0>,
                         cudaFuncAttributeMaxDynamicSharedMemorySize, GEMM_SMEM_BYTES);
    cudaFuncSetAttribute(mma_gemm_kernel<1>,
                         cudaFuncAttributeMaxDynamicSharedMemorySize, GEMM_SMEM_BYTES);

    int nblk_aggw = (N_NODES * 32 + 255) / 256;   // one warp per node
    int nblk_gemm = (N_NODES + 127) / 128;        // 782

    // K1-K4: preprocessing (deterministic each call; degs were reset by
    // the previous call's scan_final — zeroed-counter invariant)
    count_w_kernel<<<128 + NB_EDGES4, 256>>>(src, dst, W1, W2);
    scan_block_sums_kernel<<<NPART, SCAN_B>>>();
    scan_final_kernel<<<NPART, SCAN_B>>>();
    fill_conv_kernel<<<NB_EDGES4 + NB_CONV, 256>>>(src, dst, features);

    // K5-K6: layer 1   (h16 -> a16 -> h16)
    aggregate16_kernel<<<nblk_aggw, 256>>>(h16, a16);
    mma_gemm_kernel<1><<<nblk_gemm, 256, GEMM_SMEM_BYTES>>>(a16, wh, b1, nullptr, h16);

    // K7-K8: layer 2   (h16 -> a16 -> out fp32)
    aggregate16_kernel<<<nblk_aggw, 256>>>(h16, a16);
    mma_gemm_kernel<0><<<nblk_gemm, 256, GEMM_SMEM_BYTES>>>(a16, wh + 128 * 128, b2, out, nullptr);
}